// round 4
// baseline (speedup 1.0000x reference)
#include <cuda_runtime.h>

#define D        128
#define MAX_N    50000
#define TILE_M   64          // node rows per MLP block
#define MLP_THREADS 256

// Scratch for aggregated messages (static __device__ globals: allowed, no cudaMalloc)
__device__ float g_mi[MAX_N * D];
__device__ float g_mo[MAX_N * D];
__device__ int   g_idx_is64;   // 1 -> edge_index buffer is int64, 0 -> int32

// ---------------------------------------------------------------------------
// Kernel 0: detect edge_index dtype (int64 vs int32-narrowed by harness).
//   Samples 64 int64 slots within the first E slots (safe under both layouts:
//   int64 buffer has 2E slots, int32 buffer reinterpreted has E slots).
//   If the data is int32 pairs, the packed high word is >=1 w.p. 1-1/N.
// ---------------------------------------------------------------------------
__global__ void detect_idx_kernel(const void* __restrict__ eidx, int E, int N) {
    if (threadIdx.x != 0 || blockIdx.x != 0) return;
    const long long* p64 = (const long long*)eidx;
    int stride = E / 64; if (stride < 1) stride = 1;
    int ok = 1;
    for (int i = 0; i < 64; ++i) {
        long long v = p64[(long long)i * stride];
        if (v < 0 || v >= N) { ok = 0; break; }
    }
    g_idx_is64 = ok;
}

// ---------------------------------------------------------------------------
// Kernel 1: zero the message buffers (float4 stores)
// ---------------------------------------------------------------------------
__global__ void zero_kernel(int n4) {
    int i = blockIdx.x * blockDim.x + threadIdx.x;
    if (i < n4) {
        float4 z = make_float4(0.f, 0.f, 0.f, 0.f);
        reinterpret_cast<float4*>(g_mi)[i] = z;
        reinterpret_cast<float4*>(g_mo)[i] = z;
    }
}

// ---------------------------------------------------------------------------
// Kernel 2: edge scatter. One warp per edge; lane l owns floats [4l,4l+4).
//   mi[dst] += e * x[src];  mo[src] += e * x[dst]
//   red.global.add.v4.f32 (sm_90+): fire-and-forget, 1 insn per 16 B.
// ---------------------------------------------------------------------------
__device__ __forceinline__ void red_add_v4(float* p, float a, float b, float c, float d) {
    asm volatile("red.global.add.v4.f32 [%0], {%1, %2, %3, %4};"
                 :: "l"(p), "f"(a), "f"(b), "f"(c), "f"(d) : "memory");
}

__global__ void scatter_kernel(const float* __restrict__ x,
                               const float* __restrict__ ew,
                               const void* __restrict__ eidx,
                               int E, int N) {
    int gtid = blockIdx.x * blockDim.x + threadIdx.x;
    int edge = gtid >> 5;
    int lane = threadIdx.x & 31;
    if (edge >= E) return;

    int src, dst;
    if (g_idx_is64) {
        const long long* p = (const long long*)eidx;
        src = (int)p[edge];
        dst = (int)p[(size_t)E + edge];
    } else {
        const int* p = (const int*)eidx;
        src = p[edge];
        dst = p[(size_t)E + edge];
    }
    // crash-proofing: clamp (no-op when detection is right)
    src = min(max(src, 0), N - 1);
    dst = min(max(dst, 0), N - 1);

    float w = ew[edge];

    const float4 vs = reinterpret_cast<const float4*>(x + (size_t)src * D)[lane];
    const float4 vd = reinterpret_cast<const float4*>(x + (size_t)dst * D)[lane];

    float* pi = g_mi + (size_t)dst * D + lane * 4;
    float* po = g_mo + (size_t)src * D + lane * 4;

    red_add_v4(pi, w * vs.x, w * vs.y, w * vs.z, w * vs.w);
    red_add_v4(po, w * vd.x, w * vd.y, w * vd.z, w * vd.w);
}

// ---------------------------------------------------------------------------
// Kernel 3: fused 4-layer MLP. Block computes TILE_M=64 rows.
//   W (128x128, 64 KB) + H tile (64x128, 32 KB) in SMEM; each thread owns an
//   8-row x 4-col register tile: 32 FMA per k-step.
// ---------------------------------------------------------------------------
__global__ __launch_bounds__(MLP_THREADS)
void mlp_kernel(const float* __restrict__ x,
                const float* __restrict__ W1, const float* __restrict__ b1,
                const float* __restrict__ W2, const float* __restrict__ b2,
                const float* __restrict__ W3, const float* __restrict__ b3,
                const float* __restrict__ W4, const float* __restrict__ b4,
                float* __restrict__ out, int N) {
    extern __shared__ float smem[];
    float* sW = smem;            // 128*128 floats = 64 KB
    float* sH = smem + D * D;    // 64*128  floats = 32 KB

    const int tid = threadIdx.x;
    const int cx  = tid & 31;    // column group: cols [4*cx, 4*cx+4)
    const int ry  = tid >> 5;    // row group:    rows [8*ry, 8*ry+8)
    const int r0  = blockIdx.x * TILE_M;

    float4 acc[8];

    auto loadW = [&](const float* __restrict__ W) {
        const float4* w4 = reinterpret_cast<const float4*>(W);
        float4* s4 = reinterpret_cast<float4*>(sW);
        #pragma unroll
        for (int i = 0; i < (D * D / 4) / MLP_THREADS; ++i)
            s4[tid + i * MLP_THREADS] = w4[tid + i * MLP_THREADS];
    };
    auto loadH = [&](const float* __restrict__ src) {
        float4* s4 = reinterpret_cast<float4*>(sH);
        #pragma unroll
        for (int i = 0; i < (TILE_M * D / 4) / MLP_THREADS; ++i) {
            int idx = tid + i * MLP_THREADS;   // float4 index in tile
            int row = idx >> 5;                // 32 float4 per row
            int col = idx & 31;
            int gr  = r0 + row;
            float4 v = make_float4(0.f, 0.f, 0.f, 0.f);
            if (gr < N)
                v = reinterpret_cast<const float4*>(src + (size_t)gr * D)[col];
            s4[idx] = v;
        }
    };

    auto gemm_acc = [&]() {
        #pragma unroll 4
        for (int k = 0; k < D; ++k) {
            float4 w = reinterpret_cast<const float4*>(sW + k * D)[cx];
            #pragma unroll
            for (int r = 0; r < 8; ++r) {
                float a = sH[(ry * 8 + r) * D + k];   // warp-broadcast
                acc[r].x = fmaf(a, w.x, acc[r].x);
                acc[r].y = fmaf(a, w.y, acc[r].y);
                acc[r].z = fmaf(a, w.z, acc[r].z);
                acc[r].w = fmaf(a, w.w, acc[r].w);
            }
        }
    };

    // ====================== Layer 1: [mi, mo, x] @ W1 =====================
    {
        float4 bv = reinterpret_cast<const float4*>(b1)[cx];
        #pragma unroll
        for (int r = 0; r < 8; ++r) acc[r] = bv;
    }
    #pragma unroll 1
    for (int p = 0; p < 3; ++p) {
        __syncthreads();                         // prior sW/sH reads complete
        loadH(p == 0 ? (const float*)g_mi : p == 1 ? (const float*)g_mo : x);
        loadW(W1 + (size_t)p * D * D);
        __syncthreads();
        gemm_acc();
    }
    __syncthreads();                             // all sH reads done
    #pragma unroll
    for (int r = 0; r < 8; ++r) {
        float4 v;
        v.x = tanhf(acc[r].x); v.y = tanhf(acc[r].y);
        v.z = tanhf(acc[r].z); v.w = tanhf(acc[r].w);
        reinterpret_cast<float4*>(sH + (ry * 8 + r) * D)[cx] = v;
    }

    // ====================== Layers 2..4 ===================================
    const float* Ws[3] = { W2, W3, W4 };
    const float* bs[3] = { b2, b3, b4 };
    #pragma unroll 1
    for (int l = 0; l < 3; ++l) {
        __syncthreads();                         // sH writes visible, prev sW reads done
        loadW(Ws[l]);
        __syncthreads();
        float4 bv = reinterpret_cast<const float4*>(bs[l])[cx];
        #pragma unroll
        for (int r = 0; r < 8; ++r) acc[r] = bv;
        gemm_acc();
        __syncthreads();                         // all sH/sW reads done
        if (l < 2) {
            #pragma unroll
            for (int r = 0; r < 8; ++r) {
                float4 v;
                v.x = tanhf(acc[r].x); v.y = tanhf(acc[r].y);
                v.z = tanhf(acc[r].z); v.w = tanhf(acc[r].w);
                reinterpret_cast<float4*>(sH + (ry * 8 + r) * D)[cx] = v;
            }
        } else {
            #pragma unroll
            for (int r = 0; r < 8; ++r) {
                int gr = r0 + ry * 8 + r;
                if (gr < N) {
                    float4 v;
                    v.x = tanhf(acc[r].x); v.y = tanhf(acc[r].y);
                    v.z = tanhf(acc[r].z); v.w = tanhf(acc[r].w);
                    reinterpret_cast<float4*>(out + (size_t)gr * D)[cx] = v;
                }
            }
        }
    }
}

// ---------------------------------------------------------------------------
// Host launcher (graph-capturable: kernel launches only)
// ---------------------------------------------------------------------------
extern "C" void kernel_launch(void* const* d_in, const int* in_sizes, int n_in,
                              void* d_out, int out_size) {
    const float* x    = (const float*)d_in[0];
    const float* ew   = (const float*)d_in[1];
    const void*  eidx = d_in[2];
    const float* W1   = (const float*)d_in[3];
    const float* b1   = (const float*)d_in[4];
    const float* W2   = (const float*)d_in[5];
    const float* b2   = (const float*)d_in[6];
    const float* W3   = (const float*)d_in[7];
    const float* b3   = (const float*)d_in[8];
    const float* W4   = (const float*)d_in[9];
    const float* b4   = (const float*)d_in[10];
    float*       out  = (float*)d_out;

    const int N = in_sizes[0] / D;        // 50000
    const int E = in_sizes[2] / 2;        // 800000

    // 0) detect index dtype
    detect_idx_kernel<<<1, 32>>>(eidx, E, N);

    // 1) zero message buffers
    {
        int n4 = N * D / 4;
        zero_kernel<<<(n4 + 255) / 256, 256>>>(n4);
    }

    // 2) edge scatter: one warp per edge
    {
        long long total = (long long)E * 32;
        int blocks = (int)((total + 255) / 256);
        scatter_kernel<<<blocks, 256>>>(x, ew, eidx, E, N);
    }

    // 3) fused MLP
    {
        const int smem = (D * D + TILE_M * D) * (int)sizeof(float);  // 98304 B
        cudaFuncSetAttribute(mlp_kernel,
                             cudaFuncAttributeMaxDynamicSharedMemorySize, smem);
        int blocks = (N + TILE_M - 1) / TILE_M;                      // 782
        mlp_kernel<<<blocks, MLP_THREADS, smem>>>(x, W1, b1, W2, b2,
                                                  W3, b3, W4, b4, out, N);
    }
}